// round 13
// baseline (speedup 1.0000x reference)
#include <cuda_runtime.h>
#include <cuda_fp16.h>
#include <math.h>
#include <cstdint>

// Problem constants
#define BATCH   2048
#define LAT     256
#define HID     1024
#define OUTD    512
#define TSTEPS  100
#define NSUB    10
#define NCTA    256
#define NTHR    256
#define NGRP    32          // independent batch groups (64 rows each)
#define GSZ     8           // CTAs per group

enum { MODE_ELU = 0, MODE_EULER = 1, MODE_PLAIN = 2 };

// ---------------------------------------------------------------------------
// Device scratch (no cudaMalloc allowed)
// ---------------------------------------------------------------------------
__device__ __align__(256) float g_zs[(size_t)TSTEPS * BATCH * LAT];
__device__ __align__(256) float g_za[(size_t)BATCH * LAT];
__device__ __align__(256) float g_zb[(size_t)BATCH * LAT];
__device__ __align__(256) float g_Md[(size_t)OUTD * LAT];
__device__ __align__(256) float g_cd[OUTD];

// Activations stored PRE-SPLIT as fp16 hi/lo (bit-identical to consumer split)
__device__ __align__(256) __half g_h1h[(size_t)BATCH * HID], g_h1l[(size_t)BATCH * HID];
__device__ __align__(256) __half g_h2h[(size_t)BATCH * HID], g_h2l[(size_t)BATCH * HID];
__device__ __align__(256) __half g_zsh[(size_t)BATCH * LAT], g_zsl[(size_t)BATCH * LAT];

// Pre-split weights: fp16 hi/lo (hi = rn(x), lo = rn(x - hi))
__device__ __align__(256) __half g_w1h[(size_t)HID * LAT],  g_w1l[(size_t)HID * LAT];
__device__ __align__(256) __half g_w2h[(size_t)HID * HID],  g_w2l[(size_t)HID * HID];
__device__ __align__(256) __half g_w3h[(size_t)LAT * HID],  g_w3l[(size_t)LAT * HID];
__device__ __align__(256) __half g_Mdh[(size_t)OUTD * LAT], g_Mdl[(size_t)OUTD * LAT];

// Per-group barrier state: one 128B line per group. Returns to 0 every launch.
__device__ __align__(256) unsigned g_gcnt[NGRP * 32];
__device__ __align__(256) unsigned g_gsense[NGRP * 32];

// Smem: 2 buffers x 4 tiles (Ah,Al,Bh,Bl); tile = 128 rows x 20 half2
// (16 half2 payload = one K32 chunk + 4 pad). Frag LDS bank = (20r+k) mod 32
// is a bijection over the 8-row x 4-kb lane pattern -> conflict-free.
#define SA       20                    // half2 per row
#define TILE_H   (128 * SA)            // half2 per tile
#define BUF_H    (4 * TILE_H)          // half2 per buffer
#define TILE_B   (TILE_H * 4)          // bytes per tile
#define SMEM_BYTES (2 * BUF_H * 4)     // 81920 B -> 2 CTAs/SM

// ---------------------------------------------------------------------------
// Helpers
// ---------------------------------------------------------------------------
__device__ __forceinline__ uint32_t smem_u32(const void* p) {
    uint32_t a;
    asm("{ .reg .u64 t; cvta.to.shared.u64 t, %1; cvt.u32.u64 %0, t; }" : "=r"(a) : "l"(p));
    return a;
}

__device__ __forceinline__ void cp16(uint32_t dst, const void* src) {
    asm volatile("cp.async.cg.shared.global [%0], [%1], 16;" :: "r"(dst), "l"(src));
}
#define CP_COMMIT() asm volatile("cp.async.commit_group;" ::: "memory")
#define CP_WAIT0()  asm volatile("cp.async.wait_group 0;" ::: "memory")

// D += A*B (m16n8k16 fp16 inputs, fp32 accumulate)
__device__ __forceinline__ void mma16(float (&d)[4],
                                      uint32_t a0, uint32_t a1, uint32_t a2, uint32_t a3,
                                      uint32_t b0, uint32_t b1) {
    asm volatile(
        "mma.sync.aligned.m16n8k16.row.col.f32.f16.f16.f32 "
        "{%0,%1,%2,%3}, {%4,%5,%6,%7}, {%8,%9}, {%0,%1,%2,%3};"
        : "+f"(d[0]), "+f"(d[1]), "+f"(d[2]), "+f"(d[3])
        : "r"(a0), "r"(a1), "r"(a2), "r"(a3), "r"(b0), "r"(b1));
}

// split 2 floats into hi/lo packed half2 bit patterns (x -> low 16 bits)
__device__ __forceinline__ void split2(float x, float y, uint32_t& hi, uint32_t& lo) {
    __half hx = __float2half_rn(x), hy = __float2half_rn(y);
    __half lx = __float2half_rn(x - __half2float(hx));
    __half ly = __float2half_rn(y - __half2float(hy));
    hi = (uint32_t)__half_as_ushort(hx) | ((uint32_t)__half_as_ushort(hy) << 16);
    lo = (uint32_t)__half_as_ushort(lx) | ((uint32_t)__half_as_ushort(ly) << 16);
}

// ---------------------------------------------------------------------------
// Group barrier: 8 arrivals, release/acquire at gpu scope, per-group lines.
// ---------------------------------------------------------------------------
__device__ __forceinline__ void group_sync(unsigned* s_sense, int grp) {
    __syncthreads();
    if (threadIdx.x == 0) {
        unsigned* cnt = &g_gcnt[grp * 32];
        unsigned* sen = &g_gsense[grp * 32];
        unsigned my = *s_sense ^ 1u;
        *s_sense = my;
        unsigned old;
        asm volatile("atom.release.gpu.global.add.u32 %0, [%1], %2;"
                     : "=r"(old) : "l"(cnt), "r"(1u) : "memory");
        if (old == GSZ - 1u) {
            asm volatile("st.relaxed.gpu.global.u32 [%0], %1;" :: "l"(cnt), "r"(0u) : "memory");
            asm volatile("st.release.gpu.global.u32 [%0], %1;" :: "l"(sen), "r"(my) : "memory");
        } else {
            unsigned cur;
            do {
                asm volatile("ld.acquire.gpu.global.u32 %0, [%1];"
                             : "=r"(cur) : "l"(sen) : "memory");
            } while (cur != my);
        }
    }
    __syncthreads();
}

// ---------------------------------------------------------------------------
// One BM x BN output tile:  C[m,n] = epilogue( sum_k A[m,k]*W[n,k] + bias[n] )
// 3-term fp16 split (AhBh + AhBl + AlBh), fp32 register accumulators.
// AF32=true : A fp32, split on the fly (decoder only).
// AF32=false: A pre-split fp16, streamed via cp.async like B.
// MODE_ELU  : writes pre-split fp16 hi/lo outputs (Ch/Cl).
// MODE_EULER: writes fp32 C AND pre-split Ch/Cl of the same value.
// 256 threads = 8 warps (2x4). K chunks of 32. Double-buffered smem.
// ---------------------------------------------------------------------------
template <int BM, int BN, int MODE, bool AF32>
__device__ __forceinline__ void tile_mma(
    const float* __restrict__ A32,
    const __half* __restrict__ Ahg, const __half* __restrict__ Alg,
    const __half* __restrict__ Wh, const __half* __restrict__ Wl,
    const float* __restrict__ bias, const float* __restrict__ Zp,
    float* __restrict__ C, __half* __restrict__ Ch, __half* __restrict__ Cl,
    int N, int K, float h, int mB, int nB, __half2* sm, uint32_t smb) {

    constexpr int MT = BM / 32;        // mma tiles per warp (M)
    constexpr int NT = BN / 32;        // mma tiles per warp (N)
    constexpr int WM = MT * 16;
    constexpr int WN = NT * 8;
    constexpr int AG = BM * 4 / NTHR;  // A 8-float groups per thread (fp32 path)
    constexpr int AGC = BM / 64;       // A cp16 per thread per array (fp16 path)
    constexpr int BG = BN * 4 / NTHR;  // B cp16 per thread per array

    const int tid  = threadIdx.x;
    const int lane = tid & 31;
    const int warp = tid >> 5;
    const int wmi  = warp >> 2;        // 0..1
    const int wni  = warp & 3;         // 0..3
    const int nTc  = K >> 5;

    float4 ra[AF32 ? AG : 1][2];
    float acc[MT][NT][4];
#pragma unroll
    for (int i = 0; i < MT; i++)
#pragma unroll
        for (int j = 0; j < NT; j++)
#pragma unroll
            for (int c = 0; c < 4; c++) acc[i][j][c] = 0.0f;

    auto ldgA = [&](int t) {
#pragma unroll
        for (int i = 0; i < AG; i++) {
            int idx = tid + i * NTHR, row = idx >> 2, g = idx & 3;
            const float* p = A32 + (size_t)(mB + row) * K + t * 32 + g * 8;
            ra[i][0] = __ldcg((const float4*)p);
            ra[i][1] = __ldcg((const float4*)(p + 4));
        }
    };
    auto stsA = [&](int b) {
        __half2* sAh = sm + b * BUF_H;
        __half2* sAl = sAh + TILE_H;
#pragma unroll
        for (int i = 0; i < AG; i++) {
            int idx = tid + i * NTHR, row = idx >> 2, g = idx & 3;
            uint4 hi, lo;
            split2(ra[i][0].x, ra[i][0].y, hi.x, lo.x);
            split2(ra[i][0].z, ra[i][0].w, hi.y, lo.y);
            split2(ra[i][1].x, ra[i][1].y, hi.z, lo.z);
            split2(ra[i][1].z, ra[i][1].w, hi.w, lo.w);
            const int p = row * SA + g * 4;
            *(uint4*)(sAh + p) = hi;
            *(uint4*)(sAl + p) = lo;
        }
    };
    auto cpA = [&](int t, int b) {
        const uint32_t base = smb + (uint32_t)b * (BUF_H * 4);
#pragma unroll
        for (int i = 0; i < AGC; i++) {
            int idx = tid + i * NTHR, row = idx >> 2, g = idx & 3;
            const size_t o = (size_t)(mB + row) * K + t * 32 + g * 8;
            const uint32_t d = base + (uint32_t)(row * SA + g * 4) * 4;
            cp16(d, Ahg + o);
            cp16(d + TILE_B, Alg + o);
        }
    };
    auto cpB = [&](int t, int b) {
        const uint32_t base = smb + (uint32_t)b * (BUF_H * 4) + 2 * TILE_B;
#pragma unroll
        for (int i = 0; i < BG; i++) {
            int idx = tid + i * NTHR, row = idx >> 2, c = idx & 3;
            const size_t o = (size_t)(nB + row) * K + t * 32 + c * 8;
            const uint32_t d = base + (uint32_t)(row * SA + c * 4) * 4;
            cp16(d, Wh + o);
            cp16(d + TILE_B, Wl + o);
        }
    };

    // prologue: fill buffer 0
    if (AF32) ldgA(0); else cpA(0, 0);
    cpB(0, 0);
    CP_COMMIT();
    if (AF32) stsA(0);
    CP_WAIT0();
    __syncthreads();

    const int rA = wmi * WM + (lane >> 2);
    const int rB = wni * WN + (lane >> 2);
    const int cK = lane & 3;           // half2 index within 8-half2 k16 block

    for (int t = 0; t < nTc; ++t) {
        const int cur = t & 1, nxt = cur ^ 1;
        if (t + 1 < nTc) {
            if (AF32) ldgA(t + 1); else cpA(t + 1, nxt);
            cpB(t + 1, nxt);
            CP_COMMIT();
        }

        const uint32_t* sAh = (const uint32_t*)(sm + cur * BUF_H);
        const uint32_t* sAl = sAh + TILE_H;
        const uint32_t* sBh = sAl + TILE_H;
        const uint32_t* sBl = sBh + TILE_H;

#pragma unroll
        for (int blk = 0; blk < 2; blk++) {          // two k16 blocks per chunk
            const int kb = blk * 8 + cK;
            uint32_t ah[MT][4], al[MT][4], bh[NT][2], bl[NT][2];
#pragma unroll
            for (int i = 0; i < MT; i++) {
                const int r0 = (rA + i * 16) * SA, r1 = r0 + 8 * SA;
                ah[i][0] = sAh[r0 + kb];
                ah[i][1] = sAh[r1 + kb];
                ah[i][2] = sAh[r0 + kb + 4];
                ah[i][3] = sAh[r1 + kb + 4];
                al[i][0] = sAl[r0 + kb];
                al[i][1] = sAl[r1 + kb];
                al[i][2] = sAl[r0 + kb + 4];
                al[i][3] = sAl[r1 + kb + 4];
            }
#pragma unroll
            for (int j = 0; j < NT; j++) {
                const int rn = (rB + j * 8) * SA;
                bh[j][0] = sBh[rn + kb];
                bh[j][1] = sBh[rn + kb + 4];
                bl[j][0] = sBl[rn + kb];
                bl[j][1] = sBl[rn + kb + 4];
            }
#pragma unroll
            for (int i = 0; i < MT; i++)
#pragma unroll
                for (int j = 0; j < NT; j++) {
                    mma16(acc[i][j], ah[i][0], ah[i][1], ah[i][2], ah[i][3], bh[j][0], bh[j][1]);
                    mma16(acc[i][j], ah[i][0], ah[i][1], ah[i][2], ah[i][3], bl[j][0], bl[j][1]);
                    mma16(acc[i][j], al[i][0], al[i][1], al[i][2], al[i][3], bh[j][0], bh[j][1]);
                }
        }

        if (t + 1 < nTc) {
            if (AF32) stsA(nxt);
            CP_WAIT0();
            __syncthreads();
        }
    }

    // ---- epilogue ----
#pragma unroll
    for (int i = 0; i < MT; i++) {
        const int gm0 = mB + wmi * WM + i * 16 + (lane >> 2);
#pragma unroll
        for (int j = 0; j < NT; j++) {
            const int gn = nB + wni * WN + j * 8 + (lane & 3) * 2;
            const float bi0 = __ldg(bias + gn), bi1 = __ldg(bias + gn + 1);
            float x0 = acc[i][j][0] + bi0, x1 = acc[i][j][1] + bi1;
            float x2 = acc[i][j][2] + bi0, x3 = acc[i][j][3] + bi1;
            const size_t g0 = (size_t)gm0 * N + gn;
            const size_t g1 = (size_t)(gm0 + 8) * N + gn;
            if (MODE == MODE_ELU) {
                x0 = x0 > 0.0f ? x0 : expm1f(x0);
                x1 = x1 > 0.0f ? x1 : expm1f(x1);
                x2 = x2 > 0.0f ? x2 : expm1f(x2);
                x3 = x3 > 0.0f ? x3 : expm1f(x3);
                uint32_t h01, l01, h23, l23;
                split2(x0, x1, h01, l01);
                split2(x2, x3, h23, l23);
                *(uint32_t*)(Ch + g0) = h01;
                *(uint32_t*)(Cl + g0) = l01;
                *(uint32_t*)(Ch + g1) = h23;
                *(uint32_t*)(Cl + g1) = l23;
            } else {
                if (MODE == MODE_EULER) {
                    float2 z0v = __ldcg((const float2*)(Zp + g0));
                    float2 z1v = __ldcg((const float2*)(Zp + g1));
                    x0 = z0v.x + h * x0; x1 = z0v.y + h * x1;
                    x2 = z1v.x + h * x2; x3 = z1v.y + h * x3;
                    // pre-split zout for next G1 (bit-identical to consumer split)
                    uint32_t h01, l01, h23, l23;
                    split2(x0, x1, h01, l01);
                    split2(x2, x3, h23, l23);
                    *(uint32_t*)(Ch + g0) = h01;
                    *(uint32_t*)(Cl + g0) = l01;
                    *(uint32_t*)(Ch + g1) = h23;
                    *(uint32_t*)(Cl + g1) = l23;
                }
                *(float2*)(C + g0) = make_float2(x0, x1);
                *(float2*)(C + g1) = make_float2(x2, x3);
            }
        }
    }
}

// ---------------------------------------------------------------------------
// Persistent ODE integrator: 32 groups of 8 CTAs; group g owns batch rows
// [64g, 64g+64). 2 CTAs/SM (80KB smem each). Per-group barriers: 2972 (even).
// ---------------------------------------------------------------------------
__global__ void __launch_bounds__(NTHR, 2)
ode_persistent(const float* __restrict__ z0, const float* __restrict__ tv,
               const float* __restrict__ b1, const float* __restrict__ b2,
               const float* __restrict__ b3,
               float* __restrict__ zs, float* __restrict__ za,
               float* __restrict__ zb) {
    extern __shared__ __half2 sm[];
    const uint32_t smb = smem_u32(sm);
    __shared__ unsigned s_sense;
    if (threadIdx.x == 0) s_sense = 0u;

    const int bx  = blockIdx.x;
    const int grp = bx >> 3;           // 0..31
    const int l   = bx & 7;            // 0..7

    // zs[0] rows + pre-split for this CTA's 8 rows
    {
        const size_t off = ((size_t)grp * 64 + l * 8) * LAT;
        for (int i = threadIdx.x; i < 8 * LAT / 2; i += NTHR) {
            float2 v = __ldcg((const float2*)(z0 + off) + i);
            ((float2*)(zs + off))[i] = v;
            uint32_t hi, lo;
            split2(v.x, v.y, hi, lo);
            *(uint32_t*)(g_zsh + off + 2 * i) = hi;
            *(uint32_t*)(g_zsl + off + 2 * i) = lo;
        }
    }
    group_sync(&s_sense, grp);                              // barrier 1

    const int mB1 = grp * 64, nB1 = l * 128;                // G1/G2: 64x128
    const int mB3 = grp * 64, nB3 = l * 64;                 // G3: l<4, 64x64
    const size_t BL = (size_t)BATCH * LAT;

    for (int it = 0; it < TSTEPS - 1; ++it) {
        const float hstep = (__ldg(tv + it + 1) - __ldg(tv + it)) * (1.0f / NSUB);
        for (int s = 0; s < NSUB; s++) {
            const float* zin  = (s == 0)        ? zs + (size_t)it * BL
                                                : ((s & 1) ? za : zb);
            float*       zout = (s == NSUB - 1) ? zs + (size_t)(it + 1) * BL
                                                : ((s & 1) ? zb : za);
            // h1 = elu(z @ w1.T + b1)   [K=256]  A=pre-split z
            tile_mma<64, 128, MODE_ELU, false>(
                nullptr, g_zsh, g_zsl, g_w1h, g_w1l, b1, nullptr,
                nullptr, g_h1h, g_h1l, HID, LAT, 0.f, mB1, nB1, sm, smb);
            group_sync(&s_sense, grp);
            // h2 = elu(h1 @ w2.T + b2)  [K=1024]
            tile_mma<64, 128, MODE_ELU, false>(
                nullptr, g_h1h, g_h1l, g_w2h, g_w2l, b2, nullptr,
                nullptr, g_h2h, g_h2l, HID, HID, 0.f, mB1, nB1, sm, smb);
            group_sync(&s_sense, grp);
            // zout = zin + h*(h2 @ w3.T + b3)  [K=1024] + pre-split zout
            if (l < 4)
                tile_mma<64, 64, MODE_EULER, false>(
                    nullptr, g_h2h, g_h2l, g_w3h, g_w3l, b3, zin,
                    zout, g_zsh, g_zsl, LAT, HID, hstep, mB3, nB3, sm, smb);
            group_sync(&s_sense, grp);
        }
    }
    group_sync(&s_sense, grp);   // pad -> even count (2972)
}

// ---------------------------------------------------------------------------
// Folded decoder: out = zs @ Md.T + cd   (M=204800, N=512, K=256)
// ---------------------------------------------------------------------------
__global__ void __launch_bounds__(NTHR, 1)
decoder_gemm(const float* __restrict__ zs, const float* __restrict__ cd,
             float* __restrict__ out) {
    extern __shared__ __half2 sm[];
    const uint32_t smb = smem_u32(sm);
    tile_mma<128, 128, MODE_PLAIN, true>(
        zs, nullptr, nullptr, g_Mdh, g_Mdl, cd, nullptr,
        out, nullptr, nullptr, OUTD, LAT, 0.f,
        blockIdx.y * 128, blockIdx.x * 128, sm, smb);
}

// ---------------------------------------------------------------------------
// Prep kernels
// ---------------------------------------------------------------------------
__global__ void combine_kernel(const float* __restrict__ h2o_w,
                               const float* __restrict__ l2h_w,
                               float* __restrict__ Md) {
    __shared__ float sW[16][17];
    __shared__ float sL[16][17];
    const int o = blockIdx.y * 16 + threadIdx.y;
    const int l = blockIdx.x * 16 + threadIdx.x;
    float acc = 0.0f;
    for (int h0 = 0; h0 < HID; h0 += 16) {
        sW[threadIdx.y][threadIdx.x] = h2o_w[(size_t)o * HID + h0 + threadIdx.x];
        sL[threadIdx.y][threadIdx.x] = l2h_w[(size_t)(h0 + threadIdx.y) * LAT + l];
        __syncthreads();
#pragma unroll
        for (int kk = 0; kk < 16; kk++) acc += sW[threadIdx.y][kk] * sL[kk][threadIdx.x];
        __syncthreads();
    }
    Md[(size_t)o * LAT + l] = acc;
}

__global__ void cvec_kernel(const float* __restrict__ h2o_w,
                            const float* __restrict__ l2h_b,
                            const float* __restrict__ h2o_b,
                            float* __restrict__ cd) {
    const int o = blockIdx.x * blockDim.x + threadIdx.x;
    if (o < OUTD) {
        float a = h2o_b[o];
        for (int h = 0; h < HID; h++) a += h2o_w[(size_t)o * HID + h] * l2h_b[h];
        cd[o] = a;
    }
}

__global__ void split_kernel(const float* __restrict__ w,
                             __half* __restrict__ wh, __half* __restrict__ wl, int n) {
    const int i = blockIdx.x * blockDim.x + threadIdx.x;
    if (i < n) {
        float x = w[i];
        __half hi = __float2half_rn(x);
        wh[i] = hi;
        wl[i] = __float2half_rn(x - __half2float(hi));
    }
}

// ---------------------------------------------------------------------------
// Launch order: 0 combine, 1 cvec, 2-4 splits, 5 ODE, 6 split(Md), 7 decoder.
// ---------------------------------------------------------------------------
extern "C" void kernel_launch(void* const* d_in, const int* in_sizes, int n_in,
                              void* d_out, int out_size) {
    const float* z0    = (const float*)d_in[0];
    const float* tv    = (const float*)d_in[1];
    const float* w1    = (const float*)d_in[2];
    const float* b1    = (const float*)d_in[3];
    const float* w2    = (const float*)d_in[4];
    const float* b2    = (const float*)d_in[5];
    const float* w3    = (const float*)d_in[6];
    const float* b3    = (const float*)d_in[7];
    const float* l2h_w = (const float*)d_in[8];
    const float* l2h_b = (const float*)d_in[9];
    const float* h2o_w = (const float*)d_in[10];
    const float* h2o_b = (const float*)d_in[11];
    float* out = (float*)d_out;

    float *zs, *za, *zb, *Md, *cd;
    __half *w1h, *w1l, *w2h, *w2l, *w3h, *w3l, *Mdh, *Mdl;
    cudaGetSymbolAddress((void**)&zs, g_zs);
    cudaGetSymbolAddress((void**)&za, g_za);
    cudaGetSymbolAddress((void**)&zb, g_zb);
    cudaGetSymbolAddress((void**)&Md, g_Md);
    cudaGetSymbolAddress((void**)&cd, g_cd);
    cudaGetSymbolAddress((void**)&w1h, g_w1h);
    cudaGetSymbolAddress((void**)&w1l, g_w1l);
    cudaGetSymbolAddress((void**)&w2h, g_w2h);
    cudaGetSymbolAddress((void**)&w2l, g_w2l);
    cudaGetSymbolAddress((void**)&w3h, g_w3h);
    cudaGetSymbolAddress((void**)&w3l, g_w3l);
    cudaGetSymbolAddress((void**)&Mdh, g_Mdh);
    cudaGetSymbolAddress((void**)&Mdl, g_Mdl);

    static bool attr_done = false;
    if (!attr_done) {
        cudaFuncSetAttribute(ode_persistent,
                             cudaFuncAttributeMaxDynamicSharedMemorySize, SMEM_BYTES);
        cudaFuncSetAttribute(decoder_gemm,
                             cudaFuncAttributeMaxDynamicSharedMemorySize, SMEM_BYTES);
        attr_done = true;
    }

    combine_kernel<<<dim3(LAT / 16, OUTD / 16), dim3(16, 16)>>>(h2o_w, l2h_w, Md);   // 0
    cvec_kernel<<<2, 256>>>(h2o_w, l2h_b, h2o_b, cd);                                // 1
    split_kernel<<<(HID * LAT + 255) / 256, 256>>>(w1, w1h, w1l, HID * LAT);         // 2
    split_kernel<<<(HID * HID + 255) / 256, 256>>>(w2, w2h, w2l, HID * HID);         // 3
    split_kernel<<<(LAT * HID + 255) / 256, 256>>>(w3, w3h, w3l, LAT * HID);         // 4

    ode_persistent<<<NCTA, NTHR, SMEM_BYTES>>>(z0, tv, b1, b2, b3, zs, za, zb);      // 5

    split_kernel<<<(OUTD * LAT + 255) / 256, 256>>>(Md, Mdh, Mdl, OUTD * LAT);       // 6

    decoder_gemm<<<dim3(OUTD / 128, TSTEPS * BATCH / 128), NTHR, SMEM_BYTES>>>(zs, cd, out);  // 7
}

// round 14
// speedup vs baseline: 1.1817x; 1.1817x over previous
#include <cuda_runtime.h>
#include <cuda_fp16.h>
#include <math.h>
#include <cstdint>

// Problem constants
#define BATCH   2048
#define LAT     256
#define HID     1024
#define OUTD    512
#define TSTEPS  100
#define NSUB    10
#define NCTA    128
#define NTHR    256
#define NGRP    16          // independent batch groups
#define GSZ     8           // CTAs per group

enum { MODE_ELU = 0, MODE_EULER = 1, MODE_PLAIN = 2 };

// ---------------------------------------------------------------------------
// Device scratch (no cudaMalloc allowed)
// ---------------------------------------------------------------------------
__device__ __align__(256) float g_zs[(size_t)TSTEPS * BATCH * LAT];
__device__ __align__(256) float g_za[(size_t)BATCH * LAT];
__device__ __align__(256) float g_zb[(size_t)BATCH * LAT];
__device__ __align__(256) float g_Md[(size_t)OUTD * LAT];
__device__ __align__(256) float g_cd[OUTD];

// Activations stored PRE-SPLIT as fp16 hi/lo (bit-identical to consumer split)
__device__ __align__(256) __half g_h1h[(size_t)BATCH * HID], g_h1l[(size_t)BATCH * HID];
__device__ __align__(256) __half g_h2h[(size_t)BATCH * HID], g_h2l[(size_t)BATCH * HID];

// Pre-split weights: fp16 hi/lo (hi = rn(x), lo = rn(x - hi))
__device__ __align__(256) __half g_w1h[(size_t)HID * LAT],  g_w1l[(size_t)HID * LAT];
__device__ __align__(256) __half g_w2h[(size_t)HID * HID],  g_w2l[(size_t)HID * HID];
__device__ __align__(256) __half g_w3h[(size_t)LAT * HID],  g_w3l[(size_t)LAT * HID];
__device__ __align__(256) __half g_Mdh[(size_t)OUTD * LAT], g_Mdl[(size_t)OUTD * LAT];

// Per-group barrier state: one 128B line per group. Returns to 0 every launch.
__device__ __align__(256) unsigned g_gcnt[NGRP * 32];
__device__ __align__(256) unsigned g_gsense[NGRP * 32];

// Smem: 2 buffers x 4 tiles (Ah,Al,Bh,Bl); tile = 128 rows x 36 half2
// (stride 36: proven conflict-free for 16B STS, cp.async, scalar frag LDS).
#define SA       36                    // half2 per row
#define TILE_H   (128 * SA)            // half2 per tile
#define BUF_H    (4 * TILE_H)          // half2 per buffer
#define TILE_B   (TILE_H * 4)          // bytes per tile
#define SMEM_BYTES (2 * BUF_H * 4)     // 147456 B

// ---------------------------------------------------------------------------
// Helpers
// ---------------------------------------------------------------------------
__device__ __forceinline__ uint32_t smem_u32(const void* p) {
    uint32_t a;
    asm("{ .reg .u64 t; cvta.to.shared.u64 t, %1; cvt.u32.u64 %0, t; }" : "=r"(a) : "l"(p));
    return a;
}

__device__ __forceinline__ void cp16(uint32_t dst, const void* src) {
    asm volatile("cp.async.cg.shared.global [%0], [%1], 16;" :: "r"(dst), "l"(src));
}
#define CP_COMMIT() asm volatile("cp.async.commit_group;" ::: "memory")
#define CP_WAIT0()  asm volatile("cp.async.wait_group 0;" ::: "memory")

// D += A*B (m16n8k16 fp16 inputs, fp32 accumulate)
__device__ __forceinline__ void mma16(float (&d)[4],
                                      uint32_t a0, uint32_t a1, uint32_t a2, uint32_t a3,
                                      uint32_t b0, uint32_t b1) {
    asm volatile(
        "mma.sync.aligned.m16n8k16.row.col.f32.f16.f16.f32 "
        "{%0,%1,%2,%3}, {%4,%5,%6,%7}, {%8,%9}, {%0,%1,%2,%3};"
        : "+f"(d[0]), "+f"(d[1]), "+f"(d[2]), "+f"(d[3])
        : "r"(a0), "r"(a1), "r"(a2), "r"(a3), "r"(b0), "r"(b1));
}

// split 2 floats into hi/lo packed half2 bit patterns (x -> low 16 bits)
__device__ __forceinline__ void split2(float x, float y, uint32_t& hi, uint32_t& lo) {
    __half hx = __float2half_rn(x), hy = __float2half_rn(y);
    __half lx = __float2half_rn(x - __half2float(hx));
    __half ly = __float2half_rn(y - __half2float(hy));
    hi = (uint32_t)__half_as_ushort(hx) | ((uint32_t)__half_as_ushort(hy) << 16);
    lo = (uint32_t)__half_as_ushort(lx) | ((uint32_t)__half_as_ushort(ly) << 16);
}

// ---------------------------------------------------------------------------
// Group barrier: 8 arrivals, release/acquire at gpu scope, per-group lines.
// ---------------------------------------------------------------------------
__device__ __forceinline__ void group_sync(unsigned* s_sense, int grp) {
    __syncthreads();
    if (threadIdx.x == 0) {
        unsigned* cnt = &g_gcnt[grp * 32];
        unsigned* sen = &g_gsense[grp * 32];
        unsigned my = *s_sense ^ 1u;
        *s_sense = my;
        unsigned old;
        asm volatile("atom.release.gpu.global.add.u32 %0, [%1], %2;"
                     : "=r"(old) : "l"(cnt), "r"(1u) : "memory");
        if (old == GSZ - 1u) {
            asm volatile("st.relaxed.gpu.global.u32 [%0], %1;" :: "l"(cnt), "r"(0u) : "memory");
            asm volatile("st.release.gpu.global.u32 [%0], %1;" :: "l"(sen), "r"(my) : "memory");
        } else {
            unsigned cur;
            do {
                asm volatile("ld.acquire.gpu.global.u32 %0, [%1];"
                             : "=r"(cur) : "l"(sen) : "memory");
            } while (cur != my);
        }
    }
    __syncthreads();
}

// ---------------------------------------------------------------------------
// Pre-barrier prefetch of the NEXT phase's B chunk 0 into buffer 0.
// Safe: every phase has an even chunk count, so its last chunk reads buffer 1
// and the preceding __syncthreads retired all buffer-0 reads.
// ---------------------------------------------------------------------------
template <int BN>
__device__ __forceinline__ void preB(const __half* __restrict__ Wh,
                                     const __half* __restrict__ Wl,
                                     int nB, int K, uint32_t smb) {
    constexpr int BG = BN * 4 / NTHR;
    const int tid = threadIdx.x;
    const uint32_t base = smb + 2 * TILE_B;  // buffer 0, B-hi region
#pragma unroll
    for (int i = 0; i < BG; i++) {
        int idx = tid + i * NTHR, row = idx >> 2, c = idx & 3;
        const size_t o = (size_t)(nB + row) * K + c * 8;
        const uint32_t d = base + (uint32_t)(row * SA + c * 4) * 4;
        cp16(d, Wh + o);
        cp16(d + TILE_B, Wl + o);
    }
    CP_COMMIT();
}

// ---------------------------------------------------------------------------
// One BM x BN output tile:  C[m,n] = epilogue( sum_k A[m,k]*W[n,k] + bias[n] )
// 3-term fp16 split (AhBh + AhBl + AlBh), fp32 register accumulators.
// AF32=true : A fp32, split on the fly. AF32=false: A pre-split, cp.async.
// B0PRE=true: buffer 0's B was prefetched pre-barrier by the caller.
// MODE_EULER prefetches Zp at tile start (registers), uses it in epilogue.
// 256 threads = 8 warps (2x4). K chunks of 32. Double-buffered smem.
// ---------------------------------------------------------------------------
template <int BM, int BN, int MODE, bool AF32, bool B0PRE>
__device__ __forceinline__ void tile_mma(
    const float* __restrict__ A32,
    const __half* __restrict__ Ahg, const __half* __restrict__ Alg,
    const __half* __restrict__ Wh, const __half* __restrict__ Wl,
    const float* __restrict__ bias, const float* __restrict__ Zp,
    float* __restrict__ C, __half* __restrict__ Ch, __half* __restrict__ Cl,
    int N, int K, float h, int mB, int nB, __half2* sm, uint32_t smb) {

    constexpr int MT = BM / 32;        // mma tiles per warp (M)
    constexpr int NT = BN / 32;        // mma tiles per warp (N)
    constexpr int WM = MT * 16;
    constexpr int WN = NT * 8;
    constexpr int AG = BM * 4 / NTHR;  // A 8-float groups per thread (fp32 path)
    constexpr int AGC = BM / 64;       // A cp16 per thread per array (fp16 path)
    constexpr int BG = BN * 4 / NTHR;  // B cp16 per thread per array

    const int tid  = threadIdx.x;
    const int lane = tid & 31;
    const int warp = tid >> 5;
    const int wmi  = warp >> 2;        // 0..1
    const int wni  = warp & 3;         // 0..3
    const int nTc  = K >> 5;

    float4 ra[AF32 ? AG : 1][2];
    float acc[MT][NT][4];
#pragma unroll
    for (int i = 0; i < MT; i++)
#pragma unroll
        for (int j = 0; j < NT; j++)
#pragma unroll
            for (int c = 0; c < 4; c++) acc[i][j][c] = 0.0f;

    // Euler: prefetch Zp early (written before the preceding barrier -> safe)
    float2 zp[MT][NT][2];
    if (MODE == MODE_EULER) {
#pragma unroll
        for (int i = 0; i < MT; i++) {
            const int gm0 = mB + wmi * WM + i * 16 + (lane >> 2);
#pragma unroll
            for (int j = 0; j < NT; j++) {
                const int gn = nB + wni * WN + j * 8 + (lane & 3) * 2;
                zp[i][j][0] = __ldcg((const float2*)(Zp + (size_t)gm0 * N + gn));
                zp[i][j][1] = __ldcg((const float2*)(Zp + (size_t)(gm0 + 8) * N + gn));
            }
        }
    }

    auto ldgA = [&](int t) {
#pragma unroll
        for (int i = 0; i < AG; i++) {
            int idx = tid + i * NTHR, row = idx >> 2, g = idx & 3;
            const float* p = A32 + (size_t)(mB + row) * K + t * 32 + g * 8;
            ra[i][0] = __ldcg((const float4*)p);
            ra[i][1] = __ldcg((const float4*)(p + 4));
        }
    };
    auto stsA = [&](int b) {
        __half2* sAh = sm + b * BUF_H;
        __half2* sAl = sAh + TILE_H;
#pragma unroll
        for (int i = 0; i < AG; i++) {
            int idx = tid + i * NTHR, row = idx >> 2, g = idx & 3;
            uint4 hi, lo;
            split2(ra[i][0].x, ra[i][0].y, hi.x, lo.x);
            split2(ra[i][0].z, ra[i][0].w, hi.y, lo.y);
            split2(ra[i][1].x, ra[i][1].y, hi.z, lo.z);
            split2(ra[i][1].z, ra[i][1].w, hi.w, lo.w);
            const int p = row * SA + g * 4;
            *(uint4*)(sAh + p) = hi;
            *(uint4*)(sAl + p) = lo;
        }
    };
    auto cpA = [&](int t, int b) {
        const uint32_t base = smb + (uint32_t)b * (BUF_H * 4);
#pragma unroll
        for (int i = 0; i < AGC; i++) {
            int idx = tid + i * NTHR, row = idx >> 2, g = idx & 3;
            const size_t o = (size_t)(mB + row) * K + t * 32 + g * 8;
            const uint32_t d = base + (uint32_t)(row * SA + g * 4) * 4;
            cp16(d, Ahg + o);
            cp16(d + TILE_B, Alg + o);
        }
    };
    auto cpB = [&](int t, int b) {
        const uint32_t base = smb + (uint32_t)b * (BUF_H * 4) + 2 * TILE_B;
#pragma unroll
        for (int i = 0; i < BG; i++) {
            int idx = tid + i * NTHR, row = idx >> 2, c = idx & 3;
            const size_t o = (size_t)(nB + row) * K + t * 32 + c * 8;
            const uint32_t d = base + (uint32_t)(row * SA + c * 4) * 4;
            cp16(d, Wh + o);
            cp16(d + TILE_B, Wl + o);
        }
    };

    // prologue: fill buffer 0 (B may already be in flight from pre-barrier)
    if (AF32) ldgA(0); else cpA(0, 0);
    if (!B0PRE) cpB(0, 0);
    CP_COMMIT();
    if (AF32) stsA(0);
    CP_WAIT0();
    __syncthreads();

    const int rA = wmi * WM + (lane >> 2);
    const int rB = wni * WN + (lane >> 2);
    const int cK = lane & 3;           // half2 index within 8-half2 k16 block

    for (int t = 0; t < nTc; ++t) {
        const int cur = t & 1, nxt = cur ^ 1;
        if (t + 1 < nTc) {
            if (AF32) ldgA(t + 1); else cpA(t + 1, nxt);
            cpB(t + 1, nxt);
            CP_COMMIT();
        }

        const uint32_t* sAh = (const uint32_t*)(sm + cur * BUF_H);
        const uint32_t* sAl = sAh + TILE_H;
        const uint32_t* sBh = sAl + TILE_H;
        const uint32_t* sBl = sBh + TILE_H;

#pragma unroll
        for (int blk = 0; blk < 2; blk++) {          // two k16 blocks per chunk
            const int kb = blk * 8 + cK;
            uint32_t ah[MT][4], al[MT][4], bh[NT][2], bl[NT][2];
#pragma unroll
            for (int i = 0; i < MT; i++) {
                const int r0 = (rA + i * 16) * SA, r1 = r0 + 8 * SA;
                ah[i][0] = sAh[r0 + kb];
                ah[i][1] = sAh[r1 + kb];
                ah[i][2] = sAh[r0 + kb + 4];
                ah[i][3] = sAh[r1 + kb + 4];
                al[i][0] = sAl[r0 + kb];
                al[i][1] = sAl[r1 + kb];
                al[i][2] = sAl[r0 + kb + 4];
                al[i][3] = sAl[r1 + kb + 4];
            }
#pragma unroll
            for (int j = 0; j < NT; j++) {
                const int rn = (rB + j * 8) * SA;
                bh[j][0] = sBh[rn + kb];
                bh[j][1] = sBh[rn + kb + 4];
                bl[j][0] = sBl[rn + kb];
                bl[j][1] = sBl[rn + kb + 4];
            }
#pragma unroll
            for (int i = 0; i < MT; i++)
#pragma unroll
                for (int j = 0; j < NT; j++) {
                    mma16(acc[i][j], ah[i][0], ah[i][1], ah[i][2], ah[i][3], bh[j][0], bh[j][1]);
                    mma16(acc[i][j], ah[i][0], ah[i][1], ah[i][2], ah[i][3], bl[j][0], bl[j][1]);
                    mma16(acc[i][j], al[i][0], al[i][1], al[i][2], al[i][3], bh[j][0], bh[j][1]);
                }
        }

        if (t + 1 < nTc) {
            if (AF32) stsA(nxt);
            CP_WAIT0();
            __syncthreads();
        }
    }

    // ---- epilogue ----
#pragma unroll
    for (int i = 0; i < MT; i++) {
        const int gm0 = mB + wmi * WM + i * 16 + (lane >> 2);
#pragma unroll
        for (int j = 0; j < NT; j++) {
            const int gn = nB + wni * WN + j * 8 + (lane & 3) * 2;
            const float bi0 = __ldg(bias + gn), bi1 = __ldg(bias + gn + 1);
            float x0 = acc[i][j][0] + bi0, x1 = acc[i][j][1] + bi1;
            float x2 = acc[i][j][2] + bi0, x3 = acc[i][j][3] + bi1;
            const size_t g0 = (size_t)gm0 * N + gn;
            const size_t g1 = (size_t)(gm0 + 8) * N + gn;
            if (MODE == MODE_ELU) {
                x0 = x0 > 0.0f ? x0 : expm1f(x0);
                x1 = x1 > 0.0f ? x1 : expm1f(x1);
                x2 = x2 > 0.0f ? x2 : expm1f(x2);
                x3 = x3 > 0.0f ? x3 : expm1f(x3);
                uint32_t h01, l01, h23, l23;
                split2(x0, x1, h01, l01);
                split2(x2, x3, h23, l23);
                *(uint32_t*)(Ch + g0) = h01;
                *(uint32_t*)(Cl + g0) = l01;
                *(uint32_t*)(Ch + g1) = h23;
                *(uint32_t*)(Cl + g1) = l23;
            } else {
                if (MODE == MODE_EULER) {
                    x0 = zp[i][j][0].x + h * x0; x1 = zp[i][j][0].y + h * x1;
                    x2 = zp[i][j][1].x + h * x2; x3 = zp[i][j][1].y + h * x3;
                }
                *(float2*)(C + g0) = make_float2(x0, x1);
                *(float2*)(C + g1) = make_float2(x2, x3);
            }
        }
    }
}

// ---------------------------------------------------------------------------
// Persistent ODE integrator: 16 groups of 8 CTAs; group g owns batch rows
// [128g, 128g+128). Per-group barriers: 1 + 2970 + 1 = 2972 (even).
// Weight B chunk-0 of the NEXT phase is prefetched before each barrier.
// ---------------------------------------------------------------------------
__global__ void __launch_bounds__(NTHR, 1)
ode_persistent(const float* __restrict__ z0, const float* __restrict__ tv,
               const float* __restrict__ b1, const float* __restrict__ b2,
               const float* __restrict__ b3,
               float* __restrict__ zs, float* __restrict__ za,
               float* __restrict__ zb) {
    extern __shared__ __half2 sm[];
    const uint32_t smb = smem_u32(sm);
    __shared__ unsigned s_sense;
    if (threadIdx.x == 0) s_sense = 0u;

    const int bx  = blockIdx.x;
    const int grp = bx >> 3;           // 0..15
    const int l   = bx & 7;            // 0..7

    const int mB1 = grp * 128,                 nB1 = l * 128;       // G1/G2
    const int mB3 = grp * 128 + (l >> 2) * 64, nB3 = (l & 3) * 64;  // G3

    // zs[0] rows for this group
    {
        const int rowBase = grp * 128 + l * 16;
        const float4* src = (const float4*)z0 + (size_t)rowBase * (LAT / 4);
        float4*       dst = (float4*)zs + (size_t)rowBase * (LAT / 4);
        for (int i = threadIdx.x; i < 16 * (LAT / 4); i += NTHR)
            dst[i] = __ldcg(src + i);
    }
    preB<128>(g_w1h, g_w1l, nB1, LAT, smb);   // prefetch G1 B chunk 0
    group_sync(&s_sense, grp);                              // barrier 1

    const size_t BL = (size_t)BATCH * LAT;

    for (int it = 0; it < TSTEPS - 1; ++it) {
        const float hstep = (__ldg(tv + it + 1) - __ldg(tv + it)) * (1.0f / NSUB);
        for (int s = 0; s < NSUB; s++) {
            const float* zin  = (s == 0)        ? zs + (size_t)it * BL
                                                : ((s & 1) ? za : zb);
            float*       zout = (s == NSUB - 1) ? zs + (size_t)(it + 1) * BL
                                                : ((s & 1) ? zb : za);
            // h1 = elu(z @ w1.T + b1)   [K=256]  A=fp32 z, out=pre-split h1
            tile_mma<128, 128, MODE_ELU, true, true>(
                zin, nullptr, nullptr, g_w1h, g_w1l, b1, nullptr,
                nullptr, g_h1h, g_h1l, HID, LAT, 0.f, mB1, nB1, sm, smb);
            preB<128>(g_w2h, g_w2l, nB1, HID, smb);
            group_sync(&s_sense, grp);
            // h2 = elu(h1 @ w2.T + b2)  [K=1024]
            tile_mma<128, 128, MODE_ELU, false, true>(
                nullptr, g_h1h, g_h1l, g_w2h, g_w2l, b2, nullptr,
                nullptr, g_h2h, g_h2l, HID, HID, 0.f, mB1, nB1, sm, smb);
            preB<64>(g_w3h, g_w3l, nB3, HID, smb);
            group_sync(&s_sense, grp);
            // zout = zin + h*(h2 @ w3.T + b3)  [K=1024]
            tile_mma<64, 64, MODE_EULER, false, true>(
                nullptr, g_h2h, g_h2l, g_w3h, g_w3l, b3, zin,
                zout, nullptr, nullptr, LAT, HID, hstep, mB3, nB3, sm, smb);
            preB<128>(g_w1h, g_w1l, nB1, LAT, smb);
            group_sync(&s_sense, grp);
        }
    }
    group_sync(&s_sense, grp);   // pad -> even count (2972)
}

// ---------------------------------------------------------------------------
// Folded decoder: out = zs @ Md.T + cd   (M=204800, N=512, K=256)
// ---------------------------------------------------------------------------
__global__ void __launch_bounds__(NTHR, 1)
decoder_gemm(const float* __restrict__ zs, const float* __restrict__ cd,
             float* __restrict__ out) {
    extern __shared__ __half2 sm[];
    const uint32_t smb = smem_u32(sm);
    tile_mma<128, 128, MODE_PLAIN, true, false>(
        zs, nullptr, nullptr, g_Mdh, g_Mdl, cd, nullptr,
        out, nullptr, nullptr, OUTD, LAT, 0.f,
        blockIdx.y * 128, blockIdx.x * 128, sm, smb);
}

// ---------------------------------------------------------------------------
// Prep kernels
// ---------------------------------------------------------------------------
__global__ void combine_kernel(const float* __restrict__ h2o_w,
                               const float* __restrict__ l2h_w,
                               float* __restrict__ Md) {
    __shared__ float sW[16][17];
    __shared__ float sL[16][17];
    const int o = blockIdx.y * 16 + threadIdx.y;
    const int l = blockIdx.x * 16 + threadIdx.x;
    float acc = 0.0f;
    for (int h0 = 0; h0 < HID; h0 += 16) {
        sW[threadIdx.y][threadIdx.x] = h2o_w[(size_t)o * HID + h0 + threadIdx.x];
        sL[threadIdx.y][threadIdx.x] = l2h_w[(size_t)(h0 + threadIdx.y) * LAT + l];
        __syncthreads();
#pragma unroll
        for (int kk = 0; kk < 16; kk++) acc += sW[threadIdx.y][kk] * sL[kk][threadIdx.x];
        __syncthreads();
    }
    Md[(size_t)o * LAT + l] = acc;
}

__global__ void cvec_kernel(const float* __restrict__ h2o_w,
                            const float* __restrict__ l2h_b,
                            const float* __restrict__ h2o_b,
                            float* __restrict__ cd) {
    const int o = blockIdx.x * blockDim.x + threadIdx.x;
    if (o < OUTD) {
        float a = h2o_b[o];
        for (int h = 0; h < HID; h++) a += h2o_w[(size_t)o * HID + h] * l2h_b[h];
        cd[o] = a;
    }
}

__global__ void split_kernel(const float* __restrict__ w,
                             __half* __restrict__ wh, __half* __restrict__ wl, int n) {
    const int i = blockIdx.x * blockDim.x + threadIdx.x;
    if (i < n) {
        float x = w[i];
        __half hi = __float2half_rn(x);
        wh[i] = hi;
        wl[i] = __float2half_rn(x - __half2float(hi));
    }
}

// ---------------------------------------------------------------------------
// Launch order: 0 combine, 1 cvec, 2-4 splits, 5 ODE, 6 split(Md), 7 decoder.
// ---------------------------------------------------------------------------
extern "C" void kernel_launch(void* const* d_in, const int* in_sizes, int n_in,
                              void* d_out, int out_size) {
    const float* z0    = (const float*)d_in[0];
    const float* tv    = (const float*)d_in[1];
    const float* w1    = (const float*)d_in[2];
    const float* b1    = (const float*)d_in[3];
    const float* w2    = (const float*)d_in[4];
    const float* b2    = (const float*)d_in[5];
    const float* w3    = (const float*)d_in[6];
    const float* b3    = (const float*)d_in[7];
    const float* l2h_w = (const float*)d_in[8];
    const float* l2h_b = (const float*)d_in[9];
    const float* h2o_w = (const float*)d_in[10];
    const float* h2o_b = (const float*)d_in[11];
    float* out = (float*)d_out;

    float *zs, *za, *zb, *Md, *cd;
    __half *w1h, *w1l, *w2h, *w2l, *w3h, *w3l, *Mdh, *Mdl;
    cudaGetSymbolAddress((void**)&zs, g_zs);
    cudaGetSymbolAddress((void**)&za, g_za);
    cudaGetSymbolAddress((void**)&zb, g_zb);
    cudaGetSymbolAddress((void**)&Md, g_Md);
    cudaGetSymbolAddress((void**)&cd, g_cd);
    cudaGetSymbolAddress((void**)&w1h, g_w1h);
    cudaGetSymbolAddress((void**)&w1l, g_w1l);
    cudaGetSymbolAddress((void**)&w2h, g_w2h);
    cudaGetSymbolAddress((void**)&w2l, g_w2l);
    cudaGetSymbolAddress((void**)&w3h, g_w3h);
    cudaGetSymbolAddress((void**)&w3l, g_w3l);
    cudaGetSymbolAddress((void**)&Mdh, g_Mdh);
    cudaGetSymbolAddress((void**)&Mdl, g_Mdl);

    static bool attr_done = false;
    if (!attr_done) {
        cudaFuncSetAttribute(ode_persistent,
                             cudaFuncAttributeMaxDynamicSharedMemorySize, SMEM_BYTES);
        cudaFuncSetAttribute(decoder_gemm,
                             cudaFuncAttributeMaxDynamicSharedMemorySize, SMEM_BYTES);
        attr_done = true;
    }

    combine_kernel<<<dim3(LAT / 16, OUTD / 16), dim3(16, 16)>>>(h2o_w, l2h_w, Md);   // 0
    cvec_kernel<<<2, 256>>>(h2o_w, l2h_b, h2o_b, cd);                                // 1
    split_kernel<<<(HID * LAT + 255) / 256, 256>>>(w1, w1h, w1l, HID * LAT);         // 2
    split_kernel<<<(HID * HID + 255) / 256, 256>>>(w2, w2h, w2l, HID * HID);         // 3
    split_kernel<<<(LAT * HID + 255) / 256, 256>>>(w3, w3h, w3l, LAT * HID);         // 4

    ode_persistent<<<NCTA, NTHR, SMEM_BYTES>>>(z0, tv, b1, b2, b3, zs, za, zb);      // 5

    split_kernel<<<(OUTD * LAT + 255) / 256, 256>>>(Md, Mdh, Mdl, OUTD * LAT);       // 6

    decoder_gemm<<<dim3(OUTD / 128, TSTEPS * BATCH / 128), NTHR, SMEM_BYTES>>>(zs, cd, out);  // 7
}